// round 10
// baseline (speedup 1.0000x reference)
#include <cuda_runtime.h>
#include <cuda_fp16.h>
#include <cstdint>

#define DI __device__ __forceinline__

// Problem dims
constexpr int B_    = 4;
constexpr int N_    = 4096;
constexpr int D_    = 1024;
constexpr int C_    = 4;
constexpr int M_ALL = B_ * N_;      // 16384 rows total
constexpr float SCALE = 0.03125f;   // 1/sqrt(1024)
constexpr int NTILE = N_ / 128;     // 32 score column-tiles per batch row
constexpr int NZCH  = 16;           // k_col row chunks per batch

// ---------------- scratch (__device__ globals, no runtime alloc) ----------------
__device__ __half g_xh[(size_t)M_ALL * D_];            // x fp16
__device__ __half g_wq16[(size_t)D_ * D_];             // Wq fp16 row-major [d,j]
__device__ __half g_wk16[(size_t)D_ * D_];             // Wk fp16 row-major [e,j]
__device__ __half g_Gt[(size_t)D_ * D_];               // Gt[e,d] = G[d,e], G = Wq Wk^T
__device__ __half g_P[(size_t)M_ALL * D_];             // P = x G, fp16
__device__ __half g_s16[(size_t)M_ALL * N_];           // scores fp16
__device__ float g_t[D_];                              // Wk @ bq
__device__ float g_c[M_ALL];                           // SCALE * x @ t (per-col bias)
__device__ float g_zpart[NTILE][M_ALL];                // per-tile row expsums
__device__ float g_rinv[M_ALL];                        // 1/Z_n
__device__ float g_wpart[NZCH][B_ * N_];
__device__ float g_w[B_ * N_];                         // column means of attn
__device__ float g_ypart[8][B_ * D_];
__device__ float g_y[B_ * D_];                         // y_b = sum_m w_bm x_bm
__device__ float g_pooled[B_ * D_];

// ---------------- small helpers ----------------
// fast exp on FMA pipe (no MUFU). valid for |x| < ~87. rel err ~2e-6.
DI float fast_exp(float x) {
    x = fmaxf(x, -80.0f);
    const float L2E = 1.4426950408889634f;
    float t = fmaf(x, L2E, 12582912.0f);
    float n = t - 12582912.0f;
    float r = fmaf(x, L2E, -n);
    float p = 1.3333558146428443e-3f;
    p = fmaf(p, r, 9.6181291976956254e-3f);
    p = fmaf(p, r, 5.5504108664821580e-2f);
    p = fmaf(p, r, 2.4022650695910071e-1f);
    p = fmaf(p, r, 6.9314718055994531e-1f);
    p = fmaf(p, r, 1.0f);
    int e = (int)n;
    float sc = __int_as_float((e + 127) << 23);
    return p * sc;
}

DI float warpRedSum(float v) {
    #pragma unroll
    for (int o = 16; o > 0; o >>= 1) v += __shfl_xor_sync(0xffffffffu, v, o);
    return v;
}

// ---------------- prep kernels ----------------
__global__ void k_w16(const float* __restrict__ Wq, const float* __restrict__ Wk) {
    int i = blockIdx.x * blockDim.x + threadIdx.x;     // D_*D_/2
    int i2 = i * 2;
    *reinterpret_cast<__half2*>(&g_wq16[i2]) = __floats2half2_rn(Wq[i2], Wq[i2 + 1]);
    *reinterpret_cast<__half2*>(&g_wk16[i2]) = __floats2half2_rn(Wk[i2], Wk[i2 + 1]);
}

// t[d] = sum_j Wk[d,j] * bq[j]
__global__ void k_mv1(const float* __restrict__ Wk, const float* __restrict__ bq) {
    const int d = blockIdx.x;
    const int t = threadIdx.x, lane = t & 31, wid = t >> 5;
    float s = 0.f;
    for (int j = t; j < D_; j += 256) s += Wk[(size_t)d * D_ + j] * bq[j];
    s = warpRedSum(s);
    __shared__ float red[8];
    if (lane == 0) red[wid] = s;
    __syncthreads();
    if (t == 0) {
        float tot = 0.f;
        #pragma unroll
        for (int i = 0; i < 8; ++i) tot += red[i];
        g_t[d] = tot;
    }
}

// fused: c[row] = SCALE * x[row,:] @ t  AND  g_xh = fp16(x). warp per row.
__global__ __launch_bounds__(256) void k_mv2x(const float* __restrict__ x) {
    const int row  = blockIdx.x * 8 + (threadIdx.x >> 5);
    const int lane = threadIdx.x & 31;
    const float4* xr = reinterpret_cast<const float4*>(x + (size_t)row * D_);
    const float4* tr = reinterpret_cast<const float4*>(g_t);
    uint2* xo = reinterpret_cast<uint2*>(g_xh + (size_t)row * D_);
    float s = 0.f;
    #pragma unroll
    for (int i = 0; i < 8; ++i) {
        float4 a = xr[lane + 32 * i];
        float4 b = tr[lane + 32 * i];
        s += a.x * b.x + a.y * b.y + a.z * b.z + a.w * b.w;
        __half2 h0 = __floats2half2_rn(a.x, a.y);
        __half2 h1 = __floats2half2_rn(a.z, a.w);
        uint2 o; o.x = *reinterpret_cast<uint32_t*>(&h0); o.y = *reinterpret_cast<uint32_t*>(&h1);
        xo[lane + 32 * i] = o;
    }
    s = warpRedSum(s);
    if (lane == 0) g_c[row] = SCALE * s;
}

// ---------------- HMMA GEMM (R8-proven): 128x128x32, 8 warps, 64x32 warp tiles ----------------
constexpr int BM = 128, BN = 128, BK = 32;
constexpr int LDS_ = 40;                       // padded smem row -> conflict-free ldmatrix
constexpr int BUF_BYTES = BM * LDS_ * 2;       // 10240

DI unsigned sptr(const void* p) { return (unsigned)__cvta_generic_to_shared(p); }
DI void cp16(unsigned dst, const void* src) {
    asm volatile("cp.async.cg.shared.global [%0], [%1], 16;\n" :: "r"(dst), "l"(src));
}
DI void cp_commit() { asm volatile("cp.async.commit_group;\n"); }
template<int Nn> DI void cp_wait() { asm volatile("cp.async.wait_group %0;\n" :: "n"(Nn)); }
DI void ldsm4(unsigned a, uint32_t& r0, uint32_t& r1, uint32_t& r2, uint32_t& r3) {
    asm volatile("ldmatrix.sync.aligned.m8n8.x4.shared.b16 {%0,%1,%2,%3}, [%4];\n"
                 : "=r"(r0), "=r"(r1), "=r"(r2), "=r"(r3) : "r"(a));
}
DI void mma16816(float* c, const uint32_t* a, const uint32_t* b) {
    asm volatile("mma.sync.aligned.m16n8k16.row.col.f32.f16.f16.f32 "
                 "{%0,%1,%2,%3}, {%4,%5,%6,%7}, {%8,%9}, {%0,%1,%2,%3};\n"
                 : "+f"(c[0]), "+f"(c[1]), "+f"(c[2]), "+f"(c[3])
                 : "r"(a[0]), "r"(a[1]), "r"(a[2]), "r"(a[3]), "r"(b[0]), "r"(b[1]));
}

// JOB: 0 = Gt = Wk * Wq^T ; 1 = P = xh * Gt^T ;
//      3 = scores = P * xh^T  (fp16*SCALE + c_m out, fused per-tile row expsums), batch=bzArg
template<int JOB>
__global__ __launch_bounds__(256)
void k_gemm(int bzArg)
{
    constexpr int K = D_;
    __shared__ __half smA[2][BM * LDS_];
    __shared__ __half smB[2][BN * LDS_];
    __shared__ float srow[128 * 4];            // JOB 3 only (2KB)

    const __half* A;
    const __half* Bm;
    const int bz = bzArg;
    if (JOB == 0)      { A = g_wk16; Bm = g_wq16; }
    else if (JOB == 1) { A = g_xh;   Bm = g_Gt; }
    else               { A = g_P  + (size_t)bz * N_ * D_;
                         Bm = g_xh + (size_t)bz * N_ * D_; }

    const int bm = blockIdx.y * BM;
    const int bn = blockIdx.x * BN;
    A  += (size_t)bm * K;
    Bm += (size_t)bn * K;

    const int tid = threadIdx.x, lane = tid & 31, warp = tid >> 5;
    const int wm = warp >> 2;            // 0..1
    const int wn = warp & 3;             // 0..3

    const int lrow = tid >> 2;
    const int lch  = (tid & 3) * 8;
    const unsigned sA = sptr(smA), sB = sptr(smB);
    const unsigned ldst  = (unsigned)((lrow * LDS_ + lch) * 2);
    const unsigned ldst2 = (unsigned)(((lrow + 64) * LDS_ + lch) * 2);

    auto load_tile = [&](int buf, int kt) {
        const __half* a0 = A  + (size_t)lrow * K + kt * BK + lch;
        const __half* b0 = Bm + (size_t)lrow * K + kt * BK + lch;
        unsigned o = (unsigned)(buf * BUF_BYTES);
        cp16(sA + o + ldst,  a0);
        cp16(sA + o + ldst2, a0 + (size_t)64 * K);
        cp16(sB + o + ldst,  b0);
        cp16(sB + o + ldst2, b0 + (size_t)64 * K);
    };

    const int li = lane >> 3, lr = lane & 7;
    const unsigned aLane = (unsigned)((((li & 1) * 8 + lr) * LDS_ + (li >> 1) * 8) * 2);
    const unsigned bLane = (unsigned)((((li >> 1) * 8 + lr) * LDS_ + (li & 1) * 8) * 2);
    const unsigned wmB = (unsigned)(wm * 64 * LDS_ * 2);
    const unsigned wnB = (unsigned)(wn * 32 * LDS_ * 2);

    float acc[4][4][4];
    #pragma unroll
    for (int i = 0; i < 4; i++)
        #pragma unroll
        for (int j = 0; j < 4; j++)
            #pragma unroll
            for (int q = 0; q < 4; q++) acc[i][j][q] = 0.f;

    const int KT = K / BK;   // 32
    load_tile(0, 0); cp_commit();
    load_tile(1, 1); cp_commit();
    cp_wait<1>();
    __syncthreads();

    for (int kt = 0; kt < KT; ++kt) {
        const int buf = kt & 1;
        const unsigned oA = sA + buf * BUF_BYTES;
        const unsigned oB = sB + buf * BUF_BYTES;
        #pragma unroll
        for (int ks = 0; ks < 2; ++ks) {
            uint32_t a[4][4], b[4][2];
            #pragma unroll
            for (int mi = 0; mi < 4; ++mi)
                ldsm4(oA + wmB + (unsigned)(mi * 16 * LDS_ * 2) + (unsigned)(ks * 32) + aLane,
                      a[mi][0], a[mi][1], a[mi][2], a[mi][3]);
            #pragma unroll
            for (int nj = 0; nj < 2; ++nj)
                ldsm4(oB + wnB + (unsigned)(nj * 16 * LDS_ * 2) + (unsigned)(ks * 32) + bLane,
                      b[2 * nj][0], b[2 * nj][1], b[2 * nj + 1][0], b[2 * nj + 1][1]);
            #pragma unroll
            for (int mi = 0; mi < 4; ++mi)
                #pragma unroll
                for (int ni = 0; ni < 4; ++ni)
                    mma16816(acc[mi][ni], a[mi], b[ni]);
        }
        __syncthreads();
        if (kt + 2 < KT) load_tile(buf, kt + 2);
        cp_commit();
        cp_wait<1>();
        __syncthreads();
    }

    // ---------------- epilogue ----------------
    const int row0 = bm + wm * 64 + (lane >> 2);
    const int col0 = bn + wn * 32 + (lane & 3) * 2;

    if (JOB != 3) {
        #pragma unroll
        for (int mi = 0; mi < 4; ++mi) {
            #pragma unroll
            for (int ni = 0; ni < 4; ++ni) {
                int r0 = row0 + mi * 16;
                int c  = col0 + ni * 8;
                __half* dst = (JOB == 0) ? g_Gt : g_P;
                *reinterpret_cast<__half2*>(&dst[(size_t)r0 * D_ + c]) =
                    __floats2half2_rn(acc[mi][ni][0], acc[mi][ni][1]);
                *reinterpret_cast<__half2*>(&dst[(size_t)(r0 + 8) * D_ + c]) =
                    __floats2half2_rn(acc[mi][ni][2], acc[mi][ni][3]);
            }
        }
    } else {
        // scores: s = acc*SCALE + c_bias[col]; store fp16; fused per-row expsum partials
        #pragma unroll
        for (int mi = 0; mi < 4; ++mi) {
            float rs0 = 0.f, rs1 = 0.f;
            #pragma unroll
            for (int ni = 0; ni < 4; ++ni) {
                int c  = col0 + ni * 8;
                float cb0 = g_c[bz * N_ + c];
                float cb1 = g_c[bz * N_ + c + 1];
                int r0 = row0 + mi * 16;
                float s0 = fmaf(acc[mi][ni][0], SCALE, cb0);
                float s1 = fmaf(acc[mi][ni][1], SCALE, cb1);
                float s2 = fmaf(acc[mi][ni][2], SCALE, cb0);
                float s3 = fmaf(acc[mi][ni][3], SCALE, cb1);
                *reinterpret_cast<__half2*>(&g_s16[((size_t)(bz * N_ + r0)) * N_ + c]) =
                    __floats2half2_rn(s0, s1);
                *reinterpret_cast<__half2*>(&g_s16[((size_t)(bz * N_ + r0 + 8)) * N_ + c]) =
                    __floats2half2_rn(s2, s3);
                rs0 += fast_exp(s0) + fast_exp(s1);
                rs1 += fast_exp(s2) + fast_exp(s3);
            }
            // reduce over the 4 lanes of the quad (lane&3 covers cols)
            rs0 += __shfl_xor_sync(0xffffffffu, rs0, 1);
            rs0 += __shfl_xor_sync(0xffffffffu, rs0, 2);
            rs1 += __shfl_xor_sync(0xffffffffu, rs1, 1);
            rs1 += __shfl_xor_sync(0xffffffffu, rs1, 2);
            if ((lane & 3) == 0) {
                int rl = wm * 64 + (lane >> 2) + mi * 16;
                srow[rl * 4 + wn]       = rs0;
                srow[(rl + 8) * 4 + wn] = rs1;
            }
        }
        __syncthreads();
        if (tid < 128) {
            float z = srow[tid * 4] + srow[tid * 4 + 1] + srow[tid * 4 + 2] + srow[tid * 4 + 3];
            g_zpart[blockIdx.x][bz * N_ + bm + tid] = z;
        }
    }
}

// combine per-tile expsums -> rinv (one batch)
__global__ void k_zred(int b) {
    int i = b * N_ + blockIdx.x * blockDim.x + threadIdx.x;   // N_ per batch
    float z = 0.f;
    #pragma unroll
    for (int t = 0; t < NTILE; ++t) z += g_zpart[t][i];
    g_rinv[i] = 1.0f / z;
}

// ---------------- softmax column partial means, one batch (L2-resident scores) ----------------
__global__ __launch_bounds__(256) void k_col(int b) {
    const int z = blockIdx.y;                         // 0..NZCH-1, 256 rows each
    const int col = blockIdx.x * 256 + threadIdx.x;
    const __half* S = g_s16 + (size_t)b * N_ * N_;
    const float* ri = g_rinv + b * N_;
    const int n0 = z * (N_ / NZCH);
    float a0 = 0.f, a1 = 0.f, a2 = 0.f, a3 = 0.f;
    for (int n = n0; n < n0 + (N_ / NZCH); n += 4) {
        a0 += fast_exp(__half2float(S[(size_t)(n    ) * N_ + col])) * ri[n    ];
        a1 += fast_exp(__half2float(S[(size_t)(n + 1) * N_ + col])) * ri[n + 1];
        a2 += fast_exp(__half2float(S[(size_t)(n + 2) * N_ + col])) * ri[n + 2];
        a3 += fast_exp(__half2float(S[(size_t)(n + 3) * N_ + col])) * ri[n + 3];
    }
    g_wpart[z][b * N_ + col] = (a0 + a1) + (a2 + a3);
}

__global__ void k_wreduce() {
    int i = blockIdx.x * blockDim.x + threadIdx.x;   // B_*N_
    float s = 0.f;
    #pragma unroll
    for (int z = 0; z < NZCH; ++z) s += g_wpart[z][i];
    g_w[i] = s * (1.0f / N_);
}

// ---------------- y_b = sum_m w_bm * x_bm ----------------
__global__ __launch_bounds__(256) void k_wsum(const float* __restrict__ x) {
    const int b = blockIdx.y, z = blockIdx.z;
    const int d = blockIdx.x * 256 + threadIdx.x;
    const float* X = x + (size_t)b * N_ * D_;
    const float* w = g_w + b * N_;
    const int m0 = z * 512;
    float a0 = 0.f, a1 = 0.f, a2 = 0.f, a3 = 0.f;
    for (int m = m0; m < m0 + 512; m += 4) {
        a0 += w[m    ] * X[(size_t)(m    ) * D_ + d];
        a1 += w[m + 1] * X[(size_t)(m + 1) * D_ + d];
        a2 += w[m + 2] * X[(size_t)(m + 2) * D_ + d];
        a3 += w[m + 3] * X[(size_t)(m + 3) * D_ + d];
    }
    g_ypart[z][b * D_ + d] = (a0 + a1) + (a2 + a3);
}

__global__ void k_yreduce() {
    int i = blockIdx.x * blockDim.x + threadIdx.x;   // B_*D_
    float s = 0.f;
    #pragma unroll
    for (int z = 0; z < 8; ++z) s += g_ypart[z][i];
    g_y[i] = s;
}

// ---------------- pooled_b = y_b @ Wv + bv ----------------
__global__ __launch_bounds__(256) void k_vmv(const float* __restrict__ Wv,
                                             const float* __restrict__ bv) {
    const int b = blockIdx.y;
    const int d = blockIdx.x * 256 + threadIdx.x;
    const float* y = g_y + b * D_;
    float s = 0.f;
    #pragma unroll 4
    for (int k = 0; k < D_; ++k) s += y[k] * Wv[(size_t)k * D_ + d];
    g_pooled[b * D_ + d] = s + bv[d];
}

// ---------------- classifier ----------------
__global__ void k_cls(const float* __restrict__ Wc, const float* __restrict__ bc,
                      float* __restrict__ out) {
    const int warp = threadIdx.x >> 5, lane = threadIdx.x & 31;
    const int b = warp >> 2, c = warp & 3;
    float s = 0.f;
    for (int d = lane; d < D_; d += 32) s += g_pooled[b * D_ + d] * Wc[(size_t)d * C_ + c];
    s = warpRedSum(s);
    if (lane == 0) out[b * C_ + c] = fmaxf(s + bc[c], 0.0f);
}

// ---------------- launch ----------------
extern "C" void kernel_launch(void* const* d_in, const int* in_sizes, int n_in,
                              void* d_out, int out_size) {
    const float* x  = (const float*)d_in[0];
    const float* Wk = (const float*)d_in[1];
    const float* bk = (const float*)d_in[2];
    const float* Wq = (const float*)d_in[3];
    const float* bq = (const float*)d_in[4];
    const float* Wv = (const float*)d_in[5];
    const float* bv = (const float*)d_in[6];
    const float* Wc = (const float*)d_in[7];
    const float* bc = (const float*)d_in[8];
    float* out = (float*)d_out;
    (void)bk;

    // prep
    k_w16<<<(D_ * D_ / 2) / 256, 256>>>(Wq, Wk);
    k_mv1<<<D_, 256>>>(Wk, bq);
    k_mv2x<<<M_ALL / 8, 256>>>(x);     // fused: g_c + g_xh

    // Gt = Wk * Wq^T : [1024,1024], K=1024
    dim3 gG(D_ / BN, D_ / BM, 1);
    k_gemm<0><<<gG, 256>>>(0);

    // P = xh * Gt^T : [16384,1024], K=1024
    dim3 gP1(D_ / BN, M_ALL / BM, 1);
    k_gemm<1><<<gP1, 256>>>(0);

    // per batch: scores (fused row expsums) -> zred -> col, for L2 reuse of the 32MB tile
    dim3 gS(N_ / BN, N_ / BM, 1);
    dim3 gC(N_ / 256, NZCH, 1);
    for (int b = 0; b < B_; ++b) {
        k_gemm<3><<<gS, 256>>>(b);
        k_zred<<<N_ / 256, 256>>>(b);
        k_col<<<gC, 256>>>(b);
    }
    k_wreduce<<<(B_ * N_) / 256, 256>>>();

    // y = w @ x, pooled = y @ Wv + bv, classifier
    dim3 gY(D_ / 256, B_, 8);
    k_wsum<<<gY, 256>>>(x);
    k_yreduce<<<(B_ * D_) / 256, 256>>>();
    dim3 gV(D_ / 256, B_);
    k_vmv<<<gV, 256>>>(Wv, bv);
    k_cls<<<1, 512>>>(Wc, bc, out);
}

// round 13
// speedup vs baseline: 1.0636x; 1.0636x over previous
#include <cuda_runtime.h>
#include <cuda_fp16.h>
#include <cstdint>

#define DI __device__ __forceinline__

// Problem dims
constexpr int B_    = 4;
constexpr int N_    = 4096;
constexpr int D_    = 1024;
constexpr int C_    = 4;
constexpr int M_ALL = B_ * N_;      // 16384 rows total
constexpr float SCALE = 0.03125f;   // 1/sqrt(1024)
constexpr int NTILE = N_ / 128;     // 32 score column-tiles per batch row

// ---------------- scratch (__device__ globals, no runtime alloc) ----------------
__device__ __half g_xh[(size_t)M_ALL * D_];            // x fp16
__device__ __half g_wq16[(size_t)D_ * D_];             // Wq fp16 row-major [d,j]
__device__ __half g_wk16[(size_t)D_ * D_];             // Wk fp16 row-major [e,j]
__device__ __half g_Gt[(size_t)D_ * D_];               // Gt[e,d] = G[d,e], G = Wq Wk^T
__device__ __half g_P[(size_t)M_ALL * D_];             // P = x G, fp16
__device__ __half g_s16[(size_t)M_ALL * N_];           // scores fp16
__device__ float g_t[D_];                              // Wk @ bq
__device__ float g_c[M_ALL];                           // SCALE * x @ t (per-col bias)
__device__ float g_zpart[NTILE][M_ALL];                // per-tile row expsums
__device__ float g_rinv[M_ALL];                        // 1/Z_n
__device__ float g_wpart[8][B_ * N_];
__device__ float g_w[B_ * N_];                         // column means of attn
__device__ float g_ypart[8][B_ * D_];
__device__ float g_y[B_ * D_];                         // y_b = sum_m w_bm x_bm
__device__ float g_pooled[B_ * D_];

// ---------------- small helpers ----------------
// fast exp on FMA pipe (no MUFU). valid for |x| < ~87. rel err ~2e-6.
DI float fast_exp(float x) {
    x = fmaxf(x, -80.0f);
    const float L2E = 1.4426950408889634f;
    float t = fmaf(x, L2E, 12582912.0f);
    float n = t - 12582912.0f;
    float r = fmaf(x, L2E, -n);
    float p = 1.3333558146428443e-3f;
    p = fmaf(p, r, 9.6181291976956254e-3f);
    p = fmaf(p, r, 5.5504108664821580e-2f);
    p = fmaf(p, r, 2.4022650695910071e-1f);
    p = fmaf(p, r, 6.9314718055994531e-1f);
    p = fmaf(p, r, 1.0f);
    int e = (int)n;
    float sc = __int_as_float((e + 127) << 23);
    return p * sc;
}

DI float warpRedSum(float v) {
    #pragma unroll
    for (int o = 16; o > 0; o >>= 1) v += __shfl_xor_sync(0xffffffffu, v, o);
    return v;
}

// ---------------- prep kernels (R8-proven forms) ----------------
__global__ void k_w16(const float* __restrict__ Wq, const float* __restrict__ Wk) {
    int i = blockIdx.x * blockDim.x + threadIdx.x;     // D_*D_/2
    int i2 = i * 2;
    *reinterpret_cast<__half2*>(&g_wq16[i2]) = __floats2half2_rn(Wq[i2], Wq[i2 + 1]);
    *reinterpret_cast<__half2*>(&g_wk16[i2]) = __floats2half2_rn(Wk[i2], Wk[i2 + 1]);
}

// t[d] = sum_j Wk[d,j] * bq[j]
__global__ void k_mv1(const float* __restrict__ Wk, const float* __restrict__ bq) {
    const int d = blockIdx.x;
    const int t = threadIdx.x, lane = t & 31, wid = t >> 5;
    float s = 0.f;
    for (int j = t; j < D_; j += 256) s += Wk[(size_t)d * D_ + j] * bq[j];
    s = warpRedSum(s);
    __shared__ float red[8];
    if (lane == 0) red[wid] = s;
    __syncthreads();
    if (t == 0) {
        float tot = 0.f;
        #pragma unroll
        for (int i = 0; i < 8; ++i) tot += red[i];
        g_t[d] = tot;
    }
}

// fused: c[row] = SCALE * x[row,:] @ t  AND  g_xh = fp16(x). warp per row. (ran in R9/R10)
__global__ __launch_bounds__(256) void k_mv2x(const float* __restrict__ x) {
    const int row  = blockIdx.x * 8 + (threadIdx.x >> 5);
    const int lane = threadIdx.x & 31;
    const float4* xr = reinterpret_cast<const float4*>(x + (size_t)row * D_);
    const float4* tr = reinterpret_cast<const float4*>(g_t);
    uint2* xo = reinterpret_cast<uint2*>(g_xh + (size_t)row * D_);
    float s = 0.f;
    #pragma unroll
    for (int i = 0; i < 8; ++i) {
        float4 a = xr[lane + 32 * i];
        float4 b = tr[lane + 32 * i];
        s += a.x * b.x + a.y * b.y + a.z * b.z + a.w * b.w;
        __half2 h0 = __floats2half2_rn(a.x, a.y);
        __half2 h1 = __floats2half2_rn(a.z, a.w);
        uint2 o; o.x = *reinterpret_cast<uint32_t*>(&h0); o.y = *reinterpret_cast<uint32_t*>(&h1);
        xo[lane + 32 * i] = o;
    }
    s = warpRedSum(s);
    if (lane == 0) g_c[row] = SCALE * s;
}

// ---------------- HMMA GEMM (R8-proven): 128x128x32, 8 warps, 64x32 warp tiles ----------------
constexpr int BM = 128, BN = 128, BK = 32;
constexpr int LDS_ = 40;                       // padded smem row -> conflict-free ldmatrix
constexpr int BUF_BYTES = BM * LDS_ * 2;       // 10240

DI unsigned sptr(const void* p) { return (unsigned)__cvta_generic_to_shared(p); }
DI void cp16(unsigned dst, const void* src) {
    asm volatile("cp.async.cg.shared.global [%0], [%1], 16;\n" :: "r"(dst), "l"(src));
}
DI void cp_commit() { asm volatile("cp.async.commit_group;\n"); }
template<int Nn> DI void cp_wait() { asm volatile("cp.async.wait_group %0;\n" :: "n"(Nn)); }
DI void ldsm4(unsigned a, uint32_t& r0, uint32_t& r1, uint32_t& r2, uint32_t& r3) {
    asm volatile("ldmatrix.sync.aligned.m8n8.x4.shared.b16 {%0,%1,%2,%3}, [%4];\n"
                 : "=r"(r0), "=r"(r1), "=r"(r2), "=r"(r3) : "r"(a));
}
DI void mma16816(float* c, const uint32_t* a, const uint32_t* b) {
    asm volatile("mma.sync.aligned.m16n8k16.row.col.f32.f16.f16.f32 "
                 "{%0,%1,%2,%3}, {%4,%5,%6,%7}, {%8,%9}, {%0,%1,%2,%3};\n"
                 : "+f"(c[0]), "+f"(c[1]), "+f"(c[2]), "+f"(c[3])
                 : "r"(a[0]), "r"(a[1]), "r"(a[2]), "r"(a[3]), "r"(b[0]), "r"(b[1]));
}

// JOB: 0 = Gt = Wk * Wq^T ; 1 = P = xh * Gt^T ;
//      3 = scores = P * xh^T  (fp16*SCALE + c_m out, fused per-tile row expsums), z=batch
template<int JOB>
__global__ __launch_bounds__(256)
void k_gemm()
{
    constexpr int K = D_;
    __shared__ __half smA[2][BM * LDS_];
    __shared__ __half smB[2][BN * LDS_];
    __shared__ float srow[128 * 4];            // JOB 3 only (2KB)

    const __half* A;
    const __half* Bm;
    const int bz = blockIdx.z;
    if (JOB == 0)      { A = g_wk16; Bm = g_wq16; }
    else if (JOB == 1) { A = g_xh;   Bm = g_Gt; }
    else               { A = g_P  + (size_t)bz * N_ * D_;
                         Bm = g_xh + (size_t)bz * N_ * D_; }

    const int bm = blockIdx.y * BM;
    const int bn = blockIdx.x * BN;
    A  += (size_t)bm * K;
    Bm += (size_t)bn * K;

    const int tid = threadIdx.x, lane = tid & 31, warp = tid >> 5;
    const int wm = warp >> 2;            // 0..1
    const int wn = warp & 3;             // 0..3

    const int lrow = tid >> 2;
    const int lch  = (tid & 3) * 8;
    const unsigned sA = sptr(smA), sB = sptr(smB);
    const unsigned ldst  = (unsigned)((lrow * LDS_ + lch) * 2);
    const unsigned ldst2 = (unsigned)(((lrow + 64) * LDS_ + lch) * 2);

    auto load_tile = [&](int buf, int kt) {
        const __half* a0 = A  + (size_t)lrow * K + kt * BK + lch;
        const __half* b0 = Bm + (size_t)lrow * K + kt * BK + lch;
        unsigned o = (unsigned)(buf * BUF_BYTES);
        cp16(sA + o + ldst,  a0);
        cp16(sA + o + ldst2, a0 + (size_t)64 * K);
        cp16(sB + o + ldst,  b0);
        cp16(sB + o + ldst2, b0 + (size_t)64 * K);
    };

    const int li = lane >> 3, lr = lane & 7;
    const unsigned aLane = (unsigned)((((li & 1) * 8 + lr) * LDS_ + (li >> 1) * 8) * 2);
    const unsigned bLane = (unsigned)((((li >> 1) * 8 + lr) * LDS_ + (li & 1) * 8) * 2);
    const unsigned wmB = (unsigned)(wm * 64 * LDS_ * 2);
    const unsigned wnB = (unsigned)(wn * 32 * LDS_ * 2);

    float acc[4][4][4];
    #pragma unroll
    for (int i = 0; i < 4; i++)
        #pragma unroll
        for (int j = 0; j < 4; j++)
            #pragma unroll
            for (int q = 0; q < 4; q++) acc[i][j][q] = 0.f;

    const int KT = K / BK;   // 32
    load_tile(0, 0); cp_commit();
    load_tile(1, 1); cp_commit();
    cp_wait<1>();
    __syncthreads();

    for (int kt = 0; kt < KT; ++kt) {
        const int buf = kt & 1;
        const unsigned oA = sA + buf * BUF_BYTES;
        const unsigned oB = sB + buf * BUF_BYTES;
        #pragma unroll
        for (int ks = 0; ks < 2; ++ks) {
            uint32_t a[4][4], b[4][2];
            #pragma unroll
            for (int mi = 0; mi < 4; ++mi)
                ldsm4(oA + wmB + (unsigned)(mi * 16 * LDS_ * 2) + (unsigned)(ks * 32) + aLane,
                      a[mi][0], a[mi][1], a[mi][2], a[mi][3]);
            #pragma unroll
            for (int nj = 0; nj < 2; ++nj)
                ldsm4(oB + wnB + (unsigned)(nj * 16 * LDS_ * 2) + (unsigned)(ks * 32) + bLane,
                      b[2 * nj][0], b[2 * nj][1], b[2 * nj + 1][0], b[2 * nj + 1][1]);
            #pragma unroll
            for (int mi = 0; mi < 4; ++mi)
                #pragma unroll
                for (int ni = 0; ni < 4; ++ni)
                    mma16816(acc[mi][ni], a[mi], b[ni]);
        }
        __syncthreads();
        if (kt + 2 < KT) load_tile(buf, kt + 2);
        cp_commit();
        cp_wait<1>();
        __syncthreads();
    }

    // ---------------- epilogue ----------------
    const int row0 = bm + wm * 64 + (lane >> 2);
    const int col0 = bn + wn * 32 + (lane & 3) * 2;

    if (JOB != 3) {
        #pragma unroll
        for (int mi = 0; mi < 4; ++mi) {
            #pragma unroll
            for (int ni = 0; ni < 4; ++ni) {
                int r0 = row0 + mi * 16;
                int c  = col0 + ni * 8;
                __half* dst = (JOB == 0) ? g_Gt : g_P;
                *reinterpret_cast<__half2*>(&dst[(size_t)r0 * D_ + c]) =
                    __floats2half2_rn(acc[mi][ni][0], acc[mi][ni][1]);
                *reinterpret_cast<__half2*>(&dst[(size_t)(r0 + 8) * D_ + c]) =
                    __floats2half2_rn(acc[mi][ni][2], acc[mi][ni][3]);
            }
        }
    } else {
        // scores: s = acc*SCALE + c_bias[col]; store fp16; fused per-row expsum partials
        #pragma unroll
        for (int mi = 0; mi < 4; ++mi) {
            float rs0 = 0.f, rs1 = 0.f;
            #pragma unroll
            for (int ni = 0; ni < 4; ++ni) {
                int c  = col0 + ni * 8;
                float cb0 = g_c[bz * N_ + c];
                float cb1 = g_c[bz * N_ + c + 1];
                int r0 = row0 + mi * 16;
                float s0 = fmaf(acc[mi][ni][0], SCALE, cb0);
                float s1 = fmaf(acc[mi][ni][1], SCALE, cb1);
                float s2 = fmaf(acc[mi][ni][2], SCALE, cb0);
                float s3 = fmaf(acc[mi][ni][3], SCALE, cb1);
                *reinterpret_cast<__half2*>(&g_s16[((size_t)(bz * N_ + r0)) * N_ + c]) =
                    __floats2half2_rn(s0, s1);
                *reinterpret_cast<__half2*>(&g_s16[((size_t)(bz * N_ + r0 + 8)) * N_ + c]) =
                    __floats2half2_rn(s2, s3);
                rs0 += fast_exp(s0) + fast_exp(s1);
                rs1 += fast_exp(s2) + fast_exp(s3);
            }
            // reduce over the 4 lanes of the quad (lane&3 covers cols)
            rs0 += __shfl_xor_sync(0xffffffffu, rs0, 1);
            rs0 += __shfl_xor_sync(0xffffffffu, rs0, 2);
            rs1 += __shfl_xor_sync(0xffffffffu, rs1, 1);
            rs1 += __shfl_xor_sync(0xffffffffu, rs1, 2);
            if ((lane & 3) == 0) {
                int rl = wm * 64 + (lane >> 2) + mi * 16;
                srow[rl * 4 + wn]       = rs0;
                srow[(rl + 8) * 4 + wn] = rs1;
            }
        }
        __syncthreads();
        if (tid < 128) {
            float z = srow[tid * 4] + srow[tid * 4 + 1] + srow[tid * 4 + 2] + srow[tid * 4 + 3];
            g_zpart[blockIdx.x][bz * N_ + bm + tid] = z;
        }
    }
}

// combine per-tile expsums -> rinv
__global__ void k_zred() {
    int i = blockIdx.x * blockDim.x + threadIdx.x;   // M_ALL
    float z = 0.f;
    #pragma unroll
    for (int t = 0; t < NTILE; ++t) z += g_zpart[t][i];
    g_rinv[i] = 1.0f / z;
}

// ---------------- softmax column partial means (half2-vectorized, 2 cols/thread) -----------
__global__ __launch_bounds__(256) void k_col() {
    const int b = blockIdx.y, z = blockIdx.z;
    const int cu = blockIdx.x * 256 + threadIdx.x;    // column-pair unit, 0..2047
    const int col = cu * 2;
    const __half2* S2 = reinterpret_cast<const __half2*>(g_s16 + (size_t)b * N_ * N_);
    const float* ri = g_rinv + b * N_;
    const int n0 = z * 512;
    float a0 = 0.f, b0 = 0.f, a1 = 0.f, b1 = 0.f;
    for (int n = n0; n < n0 + 512; n += 2) {
        float2 v0 = __half22float2(S2[(size_t)(n    ) * (N_ / 2) + cu]);
        float2 v1 = __half22float2(S2[(size_t)(n + 1) * (N_ / 2) + cu]);
        a0 += fast_exp(v0.x) * ri[n];
        b0 += fast_exp(v0.y) * ri[n];
        a1 += fast_exp(v1.x) * ri[n + 1];
        b1 += fast_exp(v1.y) * ri[n + 1];
    }
    g_wpart[z][b * N_ + col]     = a0 + a1;
    g_wpart[z][b * N_ + col + 1] = b0 + b1;
}

__global__ void k_wreduce() {
    int i = blockIdx.x * blockDim.x + threadIdx.x;   // B_*N_
    float s = 0.f;
    #pragma unroll
    for (int z = 0; z < 8; ++z) s += g_wpart[z][i];
    g_w[i] = s * (1.0f / N_);
}

// ---------------- y_b = sum_m w_bm * x_bm ----------------
__global__ __launch_bounds__(256) void k_wsum(const float* __restrict__ x) {
    const int b = blockIdx.y, z = blockIdx.z;
    const int d = blockIdx.x * 256 + threadIdx.x;
    const float* X = x + (size_t)b * N_ * D_;
    const float* w = g_w + b * N_;
    const int m0 = z * 512;
    float a0 = 0.f, a1 = 0.f, a2 = 0.f, a3 = 0.f;
    for (int m = m0; m < m0 + 512; m += 4) {
        a0 += w[m    ] * X[(size_t)(m    ) * D_ + d];
        a1 += w[m + 1] * X[(size_t)(m + 1) * D_ + d];
        a2 += w[m + 2] * X[(size_t)(m + 2) * D_ + d];
        a3 += w[m + 3] * X[(size_t)(m + 3) * D_ + d];
    }
    g_ypart[z][b * D_ + d] = (a0 + a1) + (a2 + a3);
}

__global__ void k_yreduce() {
    int i = blockIdx.x * blockDim.x + threadIdx.x;   // B_*D_
    float s = 0.f;
    #pragma unroll
    for (int z = 0; z < 8; ++z) s += g_ypart[z][i];
    g_y[i] = s;
}

// ---------------- pooled_b = y_b @ Wv + bv ----------------
__global__ __launch_bounds__(256) void k_vmv(const float* __restrict__ Wv,
                                             const float* __restrict__ bv) {
    const int b = blockIdx.y;
    const int d = blockIdx.x * 256 + threadIdx.x;
    const float* y = g_y + b * D_;
    float s = 0.f;
    #pragma unroll 4
    for (int k = 0; k < D_; ++k) s += y[k] * Wv[(size_t)k * D_ + d];
    g_pooled[b * D_ + d] = s + bv[d];
}

// ---------------- classifier ----------------
__global__ void k_cls(const float* __restrict__ Wc, const float* __restrict__ bc,
                      float* __restrict__ out) {
    const int warp = threadIdx.x >> 5, lane = threadIdx.x & 31;
    const int b = warp >> 2, c = warp & 3;
    float s = 0.f;
    for (int d = lane; d < D_; d += 32) s += g_pooled[b * D_ + d] * Wc[(size_t)d * C_ + c];
    s = warpRedSum(s);
    if (lane == 0) out[b * C_ + c] = fmaxf(s + bc[c], 0.0f);
}

// ---------------- launch ----------------
extern "C" void kernel_launch(void* const* d_in, const int* in_sizes, int n_in,
                              void* d_out, int out_size) {
    const float* x  = (const float*)d_in[0];
    const float* Wk = (const float*)d_in[1];
    const float* bk = (const float*)d_in[2];
    const float* Wq = (const float*)d_in[3];
    const float* bq = (const float*)d_in[4];
    const float* Wv = (const float*)d_in[5];
    const float* bv = (const float*)d_in[6];
    const float* Wc = (const float*)d_in[7];
    const float* bc = (const float*)d_in[8];
    float* out = (float*)d_out;
    (void)bk;

    // prep
    k_w16<<<(D_ * D_ / 2) / 256, 256>>>(Wq, Wk);
    k_mv1<<<D_, 256>>>(Wk, bq);
    k_mv2x<<<M_ALL / 8, 256>>>(x);     // fused: g_c + g_xh

    // Gt = Wk * Wq^T : [1024,1024], K=1024
    dim3 gG(D_ / BN, D_ / BM, 1);
    k_gemm<0><<<gG, 256>>>();

    // P = xh * Gt^T : [16384,1024], K=1024
    dim3 gP1(D_ / BN, M_ALL / BM, 1);
    k_gemm<1><<<gP1, 256>>>();

    // scores per batch: [4096,4096], K=1024, fused row expsums
    dim3 gS(N_ / BN, N_ / BM, B_);
    k_gemm<3><<<gS, 256>>>();

    // combine Z, column means
    k_zred<<<M_ALL / 256, 256>>>();
    dim3 gC(N_ / 512, B_, 8);
    k_col<<<gC, 256>>>();
    k_wreduce<<<(B_ * N_) / 256, 256>>>();

    // y = w @ x, pooled = y @ Wv + bv, classifier
    dim3 gY(D_ / 256, B_, 8);
    k_wsum<<<gY, 256>>>(x);
    k_yreduce<<<(B_ * D_) / 256, 256>>>();
    dim3 gV(D_ / 256, B_);
    k_vmv<<<gV, 256>>>(Wv, bv);
    k_cls<<<1, 512>>>(Wc, bc, out);
}